// round 2
// baseline (speedup 1.0000x reference)
#include <cuda_runtime.h>
#include <math.h>

#define NN 65536
#define NE 1048576

// ---------------- scratch (static device globals; no runtime alloc) --------
__device__ int   g_cnt[NN];
__device__ float g_dis[NN];
__device__ int   g_rowptr[NN + 1];
__device__ int   g_cursor[NN];
__device__ int   g_col[NE];
__device__ float g_enorm[NE];
__device__ int   g_bsum[64];
__device__ int   g_is64;
__device__ float g_bufA[(size_t)NN * 256];
__device__ float g_bufB[(size_t)NN * 256];

// ---------------- edge-index dtype detection -------------------------------
// If the harness stored edge_index as int64, every odd int32 word is a high
// half == 0 (values in [0, 65536)). If int32, odd words are real edge ids and
// the probability that 4096 of them are all zero is ~0.
__global__ void k_detect(const int* __restrict__ ei32) {
    __shared__ int cnt;
    if (threadIdx.x == 0) cnt = 0;
    __syncthreads();
    int nz = 0;
    for (int i = threadIdx.x; i < 4096; i += 256)
        if (ei32[2 * i + 1] != 0) nz++;
    atomicAdd(&cnt, nz);
    __syncthreads();
    if (threadIdx.x == 0) g_is64 = (cnt == 0) ? 1 : 0;
}

__device__ __forceinline__ int load_idx(const void* ei, long long pos) {
    if (g_is64) return (int)((const long long*)ei)[pos];
    return ((const int*)ei)[pos];
}

// ---------------- degree / CSR build ---------------------------------------
__global__ void k_zero_cnt() {
    int i = blockIdx.x * blockDim.x + threadIdx.x;
    if (i < NN) g_cnt[i] = 0;
}

__global__ void k_count(const void* __restrict__ ei) {
    int e = blockIdx.x * blockDim.x + threadIdx.x;
    if (e < NE) {
        int d = load_idx(ei, (long long)NE + e);
        atomicAdd(&g_cnt[d], 1);
    }
}

__global__ void k_dis() {
    int i = blockIdx.x * blockDim.x + threadIdx.x;
    if (i < NN) g_dis[i] = rsqrtf((float)(g_cnt[i] + 1));  // +1 self loop
}

// exclusive scan of g_cnt into g_rowptr: 64 blocks x 1024 (Hillis-Steele)
__global__ void k_scan_block() {
    __shared__ int sh[1024];
    int i = blockIdx.x * 1024 + threadIdx.x;
    int v = g_cnt[i];
    sh[threadIdx.x] = v;
    __syncthreads();
    for (int off = 1; off < 1024; off <<= 1) {
        int t = (threadIdx.x >= off) ? sh[threadIdx.x - off] : 0;
        __syncthreads();
        sh[threadIdx.x] += t;
        __syncthreads();
    }
    g_rowptr[i] = sh[threadIdx.x] - v;   // block-local exclusive
    if (threadIdx.x == 1023) g_bsum[blockIdx.x] = sh[1023];
}

__global__ void k_scan_partials() {  // 1 block x 64
    __shared__ int sh[64];
    int v = g_bsum[threadIdx.x];
    sh[threadIdx.x] = v;
    __syncthreads();
    for (int off = 1; off < 64; off <<= 1) {
        int t = (threadIdx.x >= off) ? sh[threadIdx.x - off] : 0;
        __syncthreads();
        sh[threadIdx.x] += t;
        __syncthreads();
    }
    g_bsum[threadIdx.x] = sh[threadIdx.x] - v;      // exclusive block offset
    if (threadIdx.x == 63) g_rowptr[NN] = sh[63];   // total == NE
}

__global__ void k_add_offsets() {
    int i = blockIdx.x * blockDim.x + threadIdx.x;
    if (i < NN) {
        int r = g_rowptr[i] + g_bsum[i >> 10];
        g_rowptr[i] = r;
        g_cursor[i] = r;
    }
}

__global__ void k_fill(const void* __restrict__ ei) {
    int e = blockIdx.x * blockDim.x + threadIdx.x;
    if (e < NE) {
        int s = load_idx(ei, e);
        int d = load_idx(ei, (long long)NE + e);
        int p = atomicAdd(&g_cursor[d], 1);
        g_col[p]   = s;
        g_enorm[p] = g_dis[s] * g_dis[d];
    }
}

// ---------------- normalized aggregation (gather, float4) ------------------
// out[i] = sum_{e: dst=i} norm_e * in[src_e]  +  dis[i]^2 * in[i]
template <int D>
__global__ void k_aggregate(const float* __restrict__ in, float* __restrict__ out) {
    constexpr int TPN = D / 4;                 // lanes per node (32 or 16)
    int node = blockIdx.x * (blockDim.x / TPN) + threadIdx.x / TPN;
    int lane = threadIdx.x % TPN;
    if (node >= NN) return;
    const float4* __restrict__ inv = (const float4*)in;
    int start = g_rowptr[node];
    int end   = g_rowptr[node + 1];
    float4 acc = make_float4(0.f, 0.f, 0.f, 0.f);
    for (int p = start; p < end; ++p) {
        int   s = g_col[p];
        float w = g_enorm[p];
        float4 v = inv[(size_t)s * TPN + lane];
        acc.x += w * v.x; acc.y += w * v.y; acc.z += w * v.z; acc.w += w * v.w;
    }
    float ds = g_dis[node];
    float w  = ds * ds;
    float4 v = inv[(size_t)node * TPN + lane];
    acc.x += w * v.x; acc.y += w * v.y; acc.z += w * v.z; acc.w += w * v.w;
    ((float4*)out)[(size_t)node * TPN + lane] = acc;
}

// ---------------- fp32 tiled GEMM: C[M,N] = A[M,K] @ W[K,N] (+bias) --------
// BM=128, BN=64, BK=16, 256 threads, each thread computes 8x4.
__global__ void k_gemm(const float* __restrict__ A, const float* __restrict__ W,
                       const float* __restrict__ bias, float* __restrict__ C,
                       int K, int N) {
    __shared__ float As[16][128];
    __shared__ float Ws[16 * 64];
    int tid = threadIdx.x;
    int tx  = tid & 15;   // N direction: 16 groups of 4 cols
    int ty  = tid >> 4;   // M direction: 16 groups of 8 rows
    int m0  = blockIdx.x * 128;
    int n0  = blockIdx.y * 64;

    float acc[8][4];
#pragma unroll
    for (int i = 0; i < 8; i++)
#pragma unroll
        for (int j = 0; j < 4; j++) acc[i][j] = 0.f;

    for (int k0 = 0; k0 < K; k0 += 16) {
#pragma unroll
        for (int i = 0; i < 2; i++) {          // A tile: 512 float4
            int vi  = tid + i * 256;
            int row = vi >> 2;
            int kv  = vi & 3;
            float4 a = *(const float4*)&A[(size_t)(m0 + row) * K + k0 + kv * 4];
            As[kv * 4 + 0][row] = a.x;
            As[kv * 4 + 1][row] = a.y;
            As[kv * 4 + 2][row] = a.z;
            As[kv * 4 + 3][row] = a.w;
        }
        {                                      // W tile: 256 float4
            int krow = tid >> 4;
            int nv   = tid & 15;
            float4 w = *(const float4*)&W[(size_t)(k0 + krow) * N + n0 + nv * 4];
            *(float4*)&Ws[krow * 64 + nv * 4] = w;
        }
        __syncthreads();
#pragma unroll
        for (int k = 0; k < 16; k++) {
            float rb[4];
            *(float4*)rb = *(float4*)&Ws[k * 64 + tx * 4];
            float ra[8];
            *(float4*)&ra[0] = *(float4*)&As[k][ty * 8];
            *(float4*)&ra[4] = *(float4*)&As[k][ty * 8 + 4];
#pragma unroll
            for (int i = 0; i < 8; i++)
#pragma unroll
                for (int j = 0; j < 4; j++) acc[i][j] += ra[i] * rb[j];
        }
        __syncthreads();
    }

    float4 bv = make_float4(0.f, 0.f, 0.f, 0.f);
    if (bias) bv = *(const float4*)&bias[n0 + tx * 4];
#pragma unroll
    for (int i = 0; i < 8; i++) {
        int row = m0 + ty * 8 + i;
        float4 o;
        o.x = acc[i][0] + bv.x;
        o.y = acc[i][1] + bv.y;
        o.z = acc[i][2] + bv.z;
        o.w = acc[i][3] + bv.w;
        *(float4*)&C[(size_t)row * N + n0 + tx * 4] = o;
    }
}

// ---------------- fused (+bias) -> ReLU -> row softmax ---------------------
template <int D>
__global__ void k_softmax(const float* __restrict__ in, const float* __restrict__ bias,
                          float* __restrict__ out) {
    int row  = blockIdx.x * (blockDim.x >> 5) + (threadIdx.x >> 5);
    int lane = threadIdx.x & 31;
    if (row >= NN) return;
    constexpr int PER = D / 32;
    float v[PER];
    float m = 0.f;  // relu floor
#pragma unroll
    for (int i = 0; i < PER; i++) {
        int c = lane + i * 32;
        float t = in[(size_t)row * D + c];
        if (bias) t += bias[c];
        t = fmaxf(t, 0.f);
        v[i] = t;
        m = fmaxf(m, t);
    }
#pragma unroll
    for (int off = 16; off; off >>= 1) m = fmaxf(m, __shfl_xor_sync(0xffffffffu, m, off));
    float s = 0.f;
#pragma unroll
    for (int i = 0; i < PER; i++) {
        v[i] = expf(v[i] - m);
        s += v[i];
    }
#pragma unroll
    for (int off = 16; off; off >>= 1) s += __shfl_xor_sync(0xffffffffu, s, off);
    float inv = 1.f / s;
#pragma unroll
    for (int i = 0; i < PER; i++)
        out[(size_t)row * D + lane + i * 32] = v[i] * inv;
}

// ---------------- launch ----------------------------------------------------
extern "C" void kernel_launch(void* const* d_in, const int* in_sizes, int n_in,
                              void* d_out, int out_size) {
    const float* x  = (const float*)d_in[0];
    const void*  ei = d_in[1];
    const float* W1 = (const float*)d_in[2];
    const float* b1 = (const float*)d_in[3];
    const float* W2 = (const float*)d_in[4];
    const float* b2 = (const float*)d_in[5];
    const float* W3 = (const float*)d_in[6];
    const float* b3 = (const float*)d_in[7];
    float* out = (float*)d_out;

    float *bufA, *bufB;
    cudaGetSymbolAddress((void**)&bufA, g_bufA);
    cudaGetSymbolAddress((void**)&bufB, g_bufB);

    // ---- graph preprocessing (recomputed every launch; deterministic work)
    k_detect<<<1, 256>>>((const int*)ei);
    k_zero_cnt<<<NN / 256, 256>>>();
    k_count<<<NE / 256, 256>>>(ei);
    k_dis<<<NN / 256, 256>>>();
    k_scan_block<<<64, 1024>>>();
    k_scan_partials<<<1, 64>>>();
    k_add_offsets<<<NN / 256, 256>>>();
    k_fill<<<NE / 256, 256>>>(ei);

    // ---- layer 1: aggregate-first (128) -> GEMM(128->256)+b1 -> relu/softmax
    k_aggregate<128><<<NN / 8, 256>>>(x, bufA);
    k_gemm<<<dim3(NN / 128, 256 / 64), 256>>>(bufA, W1, b1, bufB, 128, 256);
    k_softmax<256><<<NN / 8, 256>>>(bufB, nullptr, bufA);

    // ---- layer 2: GEMM(256->128) -> aggregate(128) -> +b2 relu/softmax
    k_gemm<<<dim3(NN / 128, 128 / 64), 256>>>(bufA, W2, nullptr, bufB, 256, 128);
    k_aggregate<128><<<NN / 8, 256>>>(bufB, bufA);
    k_softmax<128><<<NN / 8, 256>>>(bufA, b2, bufB);

    // ---- layer 3: GEMM(128->64) -> aggregate(64) -> +b3 relu/softmax -> out
    k_gemm<<<dim3(NN / 128, 64 / 64), 256>>>(bufB, W3, nullptr, bufA, 128, 64);
    k_aggregate<64><<<NN / 16, 256>>>(bufA, bufB);
    k_softmax<64><<<NN / 8, 256>>>(bufB, b3, out);
}

// round 6
// speedup vs baseline: 1.5349x; 1.5349x over previous
#include <cuda_runtime.h>
#include <math.h>

#define NN 65536
#define NE 1048576

// ---------------- scratch (static device globals; no runtime alloc) --------
__device__ int   g_cnt[NN];
__device__ float g_dis[NN];
__device__ int   g_rowptr[NN + 1];
__device__ int   g_cursor[NN];
__device__ int   g_col[NE];
__device__ float g_enorm[NE];
__device__ int   g_bsum[64];
__device__ int   g_is64;
__device__ float g_bufA[(size_t)NN * 256];
__device__ float g_bufB[(size_t)NN * 256];

// ---------------- init: zero degree counters + edge dtype detection --------
// If edge_index is int64, every odd int32 word is a zero high-half (values
// < 65536). If int32, odd words are real indices (P(all 4096 zero) ~ 0).
__global__ void k_init(const int* __restrict__ ei32) {
    int i = blockIdx.x * blockDim.x + threadIdx.x;
    if (i < NN) g_cnt[i] = 0;
    if (blockIdx.x == 0) {
        __shared__ int cnt;
        if (threadIdx.x == 0) cnt = 0;
        __syncthreads();
        int nz = 0;
        for (int j = threadIdx.x; j < 4096; j += 256)
            if (ei32[2 * j + 1] != 0) nz++;
        atomicAdd(&cnt, nz);
        __syncthreads();
        if (threadIdx.x == 0) g_is64 = (cnt == 0) ? 1 : 0;
    }
}

__device__ __forceinline__ int load_idx(const void* ei, long long pos) {
    if (g_is64) return (int)((const long long*)ei)[pos];
    return ((const int*)ei)[pos];
}

__global__ void k_count(const void* __restrict__ ei) {
    int e = blockIdx.x * blockDim.x + threadIdx.x;
    if (e < NE) {
        int d = load_idx(ei, (long long)NE + e);
        atomicAdd(&g_cnt[d], 1);
    }
}

// exclusive scan of g_cnt into g_rowptr (block-local) + fused dis = rsqrt(deg+1)
__global__ void k_scan_block() {
    __shared__ int sh[1024];
    int i = blockIdx.x * 1024 + threadIdx.x;
    int v = g_cnt[i];
    g_dis[i] = rsqrtf((float)(v + 1));  // +1 self loop
    sh[threadIdx.x] = v;
    __syncthreads();
    for (int off = 1; off < 1024; off <<= 1) {
        int t = (threadIdx.x >= off) ? sh[threadIdx.x - off] : 0;
        __syncthreads();
        sh[threadIdx.x] += t;
        __syncthreads();
    }
    g_rowptr[i] = sh[threadIdx.x] - v;
    if (threadIdx.x == 1023) g_bsum[blockIdx.x] = sh[1023];
}

__global__ void k_scan_partials() {  // 1 block x 64
    __shared__ int sh[64];
    int v = g_bsum[threadIdx.x];
    sh[threadIdx.x] = v;
    __syncthreads();
    for (int off = 1; off < 64; off <<= 1) {
        int t = (threadIdx.x >= off) ? sh[threadIdx.x - off] : 0;
        __syncthreads();
        sh[threadIdx.x] += t;
        __syncthreads();
    }
    g_bsum[threadIdx.x] = sh[threadIdx.x] - v;
    if (threadIdx.x == 63) g_rowptr[NN] = sh[63];
}

__global__ void k_add_offsets() {
    int i = blockIdx.x * blockDim.x + threadIdx.x;
    if (i < NN) {
        int r = g_rowptr[i] + g_bsum[i >> 10];
        g_rowptr[i] = r;
        g_cursor[i] = r;
    }
}

__global__ void k_fill(const void* __restrict__ ei) {
    int e = blockIdx.x * blockDim.x + threadIdx.x;
    if (e < NE) {
        int s = load_idx(ei, e);
        int d = load_idx(ei, (long long)NE + e);
        int p = atomicAdd(&g_cursor[d], 1);
        g_col[p]   = s;
        g_enorm[p] = g_dis[s] * g_dis[d];
    }
}

// ---------------- normalized aggregation (gather, float4) ------------------
template <int D>
__global__ void k_aggregate(const float* __restrict__ in, float* __restrict__ out) {
    constexpr int TPN = D / 4;
    int node = blockIdx.x * (blockDim.x / TPN) + threadIdx.x / TPN;
    int lane = threadIdx.x % TPN;
    if (node >= NN) return;
    const float4* __restrict__ inv = (const float4*)in;
    int start = g_rowptr[node];
    int end   = g_rowptr[node + 1];
    float4 acc = make_float4(0.f, 0.f, 0.f, 0.f);
    for (int p = start; p < end; ++p) {
        int   s = g_col[p];
        float w = g_enorm[p];
        float4 v = inv[(size_t)s * TPN + lane];
        acc.x += w * v.x; acc.y += w * v.y; acc.z += w * v.z; acc.w += w * v.w;
    }
    float ds = g_dis[node];
    float w  = ds * ds;
    float4 v = inv[(size_t)node * TPN + lane];
    acc.x += w * v.x; acc.y += w * v.y; acc.z += w * v.z; acc.w += w * v.w;
    ((float4*)out)[(size_t)node * TPN + lane] = acc;
}

// ---------------- tf32 tensor-core GEMM ------------------------------------
// C[M,N] = A[M,K] @ W[K,N] (+bias). BM=128, BN=64, BK=16.
// 8 warps (4 along M x 2 along N), warp tile 32x32, mma.m16n8k8 tf32.
__device__ __forceinline__ unsigned to_tf32(float x) {
    unsigned u;
    asm("cvt.rna.tf32.f32 %0, %1;" : "=r"(u) : "f"(x));
    return u;
}

__global__ void k_gemm_tc(const float* __restrict__ A, const float* __restrict__ W,
                          const float* __restrict__ bias, float* __restrict__ C,
                          int K, int N) {
    __shared__ unsigned As[128 * 20];  // [m][k], stride 20 (conflict-free frags)
    __shared__ unsigned Ws[16 * 72];   // [k][n], stride 72 (conflict-free frags)
    int tid   = threadIdx.x;
    int lane  = tid & 31;
    int warp  = tid >> 5;
    int warpM = warp & 3;
    int warpN = warp >> 2;
    int qp = lane >> 2, tq = lane & 3;
    int m0 = blockIdx.x * 128, n0 = blockIdx.y * 64;

    float acc[2][4][4];
#pragma unroll
    for (int a = 0; a < 2; a++)
#pragma unroll
        for (int b = 0; b < 4; b++)
#pragma unroll
            for (int c = 0; c < 4; c++) acc[a][b][c] = 0.f;

    for (int k0 = 0; k0 < K; k0 += 16) {
#pragma unroll
        for (int i = 0; i < 2; i++) {          // stage A tile (2048 floats)
            int v   = tid + i * 256;
            int row = v >> 2;
            int kq  = (v & 3) * 4;
            float4 a = *(const float4*)&A[(size_t)(m0 + row) * K + k0 + kq];
            unsigned* p = &As[row * 20 + kq];
            p[0] = to_tf32(a.x); p[1] = to_tf32(a.y);
            p[2] = to_tf32(a.z); p[3] = to_tf32(a.w);
        }
        {                                      // stage W tile (1024 floats)
            int krow = tid >> 4;
            int nc   = (tid & 15) * 4;
            float4 w = *(const float4*)&W[(size_t)(k0 + krow) * N + n0 + nc];
            unsigned* p = &Ws[krow * 72 + nc];
            p[0] = to_tf32(w.x); p[1] = to_tf32(w.y);
            p[2] = to_tf32(w.z); p[3] = to_tf32(w.w);
        }
        __syncthreads();
#pragma unroll
        for (int kk = 0; kk < 16; kk += 8) {
            unsigned af[2][4], bf[4][2];
#pragma unroll
            for (int mt = 0; mt < 2; mt++) {
                int r = warpM * 32 + mt * 16 + qp;
                af[mt][0] = As[r * 20 + kk + tq];
                af[mt][1] = As[(r + 8) * 20 + kk + tq];
                af[mt][2] = As[r * 20 + kk + tq + 4];
                af[mt][3] = As[(r + 8) * 20 + kk + tq + 4];
            }
#pragma unroll
            for (int nt = 0; nt < 4; nt++) {
                int c = warpN * 32 + nt * 8 + qp;
                bf[nt][0] = Ws[(kk + tq) * 72 + c];
                bf[nt][1] = Ws[(kk + tq + 4) * 72 + c];
            }
#pragma unroll
            for (int mt = 0; mt < 2; mt++)
#pragma unroll
                for (int nt = 0; nt < 4; nt++) {
                    asm volatile(
                        "mma.sync.aligned.m16n8k8.row.col.f32.tf32.tf32.f32 "
                        "{%0,%1,%2,%3}, {%4,%5,%6,%7}, {%8,%9}, {%0,%1,%2,%3};"
                        : "+f"(acc[mt][nt][0]), "+f"(acc[mt][nt][1]),
                          "+f"(acc[mt][nt][2]), "+f"(acc[mt][nt][3])
                        : "r"(af[mt][0]), "r"(af[mt][1]),
                          "r"(af[mt][2]), "r"(af[mt][3]),
                          "r"(bf[nt][0]), "r"(bf[nt][1]));
                }
        }
        __syncthreads();
    }

#pragma unroll
    for (int mt = 0; mt < 2; mt++) {
#pragma unroll
        for (int nt = 0; nt < 4; nt++) {
            int col = n0 + warpN * 32 + nt * 8 + 2 * tq;
            float b0 = bias ? bias[col] : 0.f;
            float b1 = bias ? bias[col + 1] : 0.f;
            int r = m0 + warpM * 32 + mt * 16 + qp;
            float2 v0 = make_float2(acc[mt][nt][0] + b0, acc[mt][nt][1] + b1);
            float2 v1 = make_float2(acc[mt][nt][2] + b0, acc[mt][nt][3] + b1);
            *(float2*)&C[(size_t)r * N + col] = v0;
            *(float2*)&C[(size_t)(r + 8) * N + col] = v1;
        }
    }
}

// ---------------- fused (+bias) -> ReLU -> row softmax ---------------------
template <int D>
__global__ void k_softmax(const float* __restrict__ in, const float* __restrict__ bias,
                          float* __restrict__ out) {
    int row  = blockIdx.x * (blockDim.x >> 5) + (threadIdx.x >> 5);
    int lane = threadIdx.x & 31;
    if (row >= NN) return;
    constexpr int PER = D / 32;
    float v[PER];
    float m = 0.f;
#pragma unroll
    for (int i = 0; i < PER; i++) {
        int c = lane + i * 32;
        float t = in[(size_t)row * D + c];
        if (bias) t += bias[c];
        t = fmaxf(t, 0.f);
        v[i] = t;
        m = fmaxf(m, t);
    }
#pragma unroll
    for (int off = 16; off; off >>= 1) m = fmaxf(m, __shfl_xor_sync(0xffffffffu, m, off));
    float s = 0.f;
#pragma unroll
    for (int i = 0; i < PER; i++) {
        v[i] = expf(v[i] - m);
        s += v[i];
    }
#pragma unroll
    for (int off = 16; off; off >>= 1) s += __shfl_xor_sync(0xffffffffu, s, off);
    float inv = 1.f / s;
#pragma unroll
    for (int i = 0; i < PER; i++)
        out[(size_t)row * D + lane + i * 32] = v[i] * inv;
}

// ---------------- launch ----------------------------------------------------
extern "C" void kernel_launch(void* const* d_in, const int* in_sizes, int n_in,
                              void* d_out, int out_size) {
    const float* x  = (const float*)d_in[0];
    const void*  ei = d_in[1];
    const float* W1 = (const float*)d_in[2];
    const float* b1 = (const float*)d_in[3];
    const float* W2 = (const float*)d_in[4];
    const float* b2 = (const float*)d_in[5];
    const float* W3 = (const float*)d_in[6];
    const float* b3 = (const float*)d_in[7];
    float* out = (float*)d_out;

    float *bufA, *bufB;
    cudaGetSymbolAddress((void**)&bufA, g_bufA);
    cudaGetSymbolAddress((void**)&bufB, g_bufB);

    // ---- graph preprocessing (recomputed every launch; deterministic)
    k_init<<<NN / 256, 256>>>((const int*)ei);
    k_count<<<NE / 256, 256>>>(ei);
    k_scan_block<<<64, 1024>>>();
    k_scan_partials<<<1, 64>>>();
    k_add_offsets<<<NN / 256, 256>>>();
    k_fill<<<NE / 256, 256>>>(ei);

    // ---- layer 1: aggregate(128) -> GEMM(128->256)+b1 -> relu/softmax
    k_aggregate<128><<<NN / 8, 256>>>(x, bufA);
    k_gemm_tc<<<dim3(NN / 128, 256 / 64), 256>>>(bufA, W1, b1, bufB, 128, 256);
    k_softmax<256><<<NN / 8, 256>>>(bufB, nullptr, bufA);

    // ---- layer 2: GEMM(256->128) -> aggregate(128) -> +b2 relu/softmax
    k_gemm_tc<<<dim3(NN / 128, 128 / 64), 256>>>(bufA, W2, nullptr, bufB, 256, 128);
    k_aggregate<128><<<NN / 8, 256>>>(bufB, bufA);
    k_softmax<128><<<NN / 8, 256>>>(bufA, b2, bufB);

    // ---- layer 3: GEMM(128->64) -> aggregate(64) -> +b3 relu/softmax -> out
    k_gemm_tc<<<dim3(NN / 128, 64 / 64), 256>>>(bufB, W3, nullptr, bufA, 128, 64);
    k_aggregate<64><<<NN / 16, 256>>>(bufA, bufB);
    k_softmax<64><<<NN / 8, 256>>>(bufB, b3, out);
}